// round 5
// baseline (speedup 1.0000x reference)
#include <cuda_runtime.h>
#include <cstdint>

#define NN   50000
#define EE   1600000
#define FIN  512
#define F1   64        // H1*C1
#define NH1  8
#define C2   40
#define NBLK 196       // ceil(NN/256)
#define FULLM 0xffffffffu

// ------------------------- scratch (static device memory; no allocs allowed)
__device__ float g_h1[NN * F1];
__device__ float g_as1[NN * NH1];
__device__ float g_ad1[NN * NH1];
__device__ float g_h2[NN * C2];
__device__ float g_as2[NN];
__device__ float g_ad2[NN];
__device__ int   g_deg[NN];
__device__ int   g_rowloc[NN];
__device__ int   g_bsum[256];
__device__ int   g_boff[256];
__device__ int   g_rowptr[NN + 1];
__device__ int   g_cursor[NN];
__device__ int   g_col[EE];

__device__ __forceinline__ float leaky(float v) { return v > 0.f ? v : 0.2f * v; }

__device__ __forceinline__ uint32_t f2tf(float f) {
    uint32_t u;
    asm("cvt.rna.tf32.f32 %0, %1;" : "=r"(u) : "f"(f));
    return u;
}

__device__ __forceinline__ void mma_tf32(float* d, const uint32_t* a, const uint32_t* b) {
    asm volatile(
        "mma.sync.aligned.m16n8k8.row.col.f32.tf32.tf32.f32 "
        "{%0,%1,%2,%3}, {%4,%5,%6,%7}, {%8,%9}, {%0,%1,%2,%3};"
        : "+f"(d[0]), "+f"(d[1]), "+f"(d[2]), "+f"(d[3])
        : "r"(a[0]), "r"(a[1]), "r"(a[2]), "r"(a[3]), "r"(b[0]), "r"(b[1]));
}

// ------------------------- GEMM1 (tf32 tensor cores) + fused attention coeffs
__global__ __launch_bounds__(256) void k_gemm1(const float* __restrict__ x,
                                               const float* __restrict__ W1,
                                               const float* __restrict__ attS,
                                               const float* __restrict__ attD) {
    __shared__ float sA[128][36];
    __shared__ float sB[32][72];
    __shared__ float sAs[64], sAd[64];

    const int t    = threadIdx.x;
    const int wid  = t >> 5;
    const int lane = t & 31;
    const int m0   = blockIdx.x * 128;
    const int warp_m = (wid >> 1) * 32;
    const int warp_n = (wid & 1) * 32;
    if (t < 64) { sAs[t] = attS[t]; sAd[t] = attD[t]; }

    float acc[2][4][4];
#pragma unroll
    for (int mi = 0; mi < 2; mi++)
#pragma unroll
        for (int ni = 0; ni < 4; ni++)
#pragma unroll
            for (int e = 0; e < 4; e++) acc[mi][ni][e] = 0.f;

    const int r = lane >> 2;
    const int c = lane & 3;
    const int arow = t >> 3;
    const int acol = (t & 7) * 4;

    for (int kc = 0; kc < FIN; kc += 32) {
#pragma unroll
        for (int i = 0; i < 4; i++) {
            int row = i * 32 + arow;
            int gm  = m0 + row;
            float4 v = (gm < NN) ? *(const float4*)&x[(long)gm * FIN + kc + acol]
                                 : make_float4(0.f, 0.f, 0.f, 0.f);
            float4 tv;
            tv.x = __uint_as_float(f2tf(v.x));
            tv.y = __uint_as_float(f2tf(v.y));
            tv.z = __uint_as_float(f2tf(v.z));
            tv.w = __uint_as_float(f2tf(v.w));
            *(float4*)&sA[row][acol] = tv;
        }
#pragma unroll
        for (int i = 0; i < 2; i++) {
            int f   = t + i * 256;
            int row = f >> 4;
            int c4  = (f & 15) * 4;
            float4 v = *(const float4*)&W1[(kc + row) * F1 + c4];
            float4 tv;
            tv.x = __uint_as_float(f2tf(v.x));
            tv.y = __uint_as_float(f2tf(v.y));
            tv.z = __uint_as_float(f2tf(v.z));
            tv.w = __uint_as_float(f2tf(v.w));
            *(float4*)&sB[row][c4] = tv;
        }
        __syncthreads();

#pragma unroll
        for (int ks = 0; ks < 4; ks++) {
            const int k0 = ks * 8;
            uint32_t afrag[2][4];
#pragma unroll
            for (int mi = 0; mi < 2; mi++) {
                int mm = warp_m + mi * 16;
                afrag[mi][0] = __float_as_uint(sA[mm + r][k0 + c]);
                afrag[mi][1] = __float_as_uint(sA[mm + r + 8][k0 + c]);
                afrag[mi][2] = __float_as_uint(sA[mm + r][k0 + c + 4]);
                afrag[mi][3] = __float_as_uint(sA[mm + r + 8][k0 + c + 4]);
            }
            uint32_t bfrag[4][2];
#pragma unroll
            for (int ni = 0; ni < 4; ni++) {
                int nn = warp_n + ni * 8;
                bfrag[ni][0] = __float_as_uint(sB[k0 + c][nn + r]);
                bfrag[ni][1] = __float_as_uint(sB[k0 + c + 4][nn + r]);
            }
#pragma unroll
            for (int mi = 0; mi < 2; mi++)
#pragma unroll
                for (int ni = 0; ni < 4; ni++)
                    mma_tf32(acc[mi][ni], afrag[mi], bfrag[ni]);
        }
        __syncthreads();
    }

#pragma unroll
    for (int mi = 0; mi < 2; mi++) {
        int row_g = m0 + warp_m + mi * 16 + r;
        int row_h = row_g + 8;
#pragma unroll
        for (int ni = 0; ni < 4; ni++) {
            int nn = warp_n + ni * 8;
            int col = nn + c * 2;
            if (row_g < NN)
                *(float2*)&g_h1[row_g * F1 + col] = make_float2(acc[mi][ni][0], acc[mi][ni][1]);
            if (row_h < NN)
                *(float2*)&g_h1[row_h * F1 + col] = make_float2(acc[mi][ni][2], acc[mi][ni][3]);
            float as0 = sAs[col], as1v = sAs[col + 1];
            float ad0 = sAd[col], ad1v = sAd[col + 1];
            float psg = acc[mi][ni][0] * as0 + acc[mi][ni][1] * as1v;
            float pdg = acc[mi][ni][0] * ad0 + acc[mi][ni][1] * ad1v;
            float psh = acc[mi][ni][2] * as0 + acc[mi][ni][3] * as1v;
            float pdh = acc[mi][ni][2] * ad0 + acc[mi][ni][3] * ad1v;
#pragma unroll
            for (int off = 1; off <= 2; off <<= 1) {
                psg += __shfl_xor_sync(FULLM, psg, off);
                pdg += __shfl_xor_sync(FULLM, pdg, off);
                psh += __shfl_xor_sync(FULLM, psh, off);
                pdh += __shfl_xor_sync(FULLM, pdh, off);
            }
            int h = nn >> 3;
            if (c == 0) {
                if (row_g < NN) { g_as1[row_g * NH1 + h] = psg; g_ad1[row_g * NH1 + h] = pdg; }
                if (row_h < NN) { g_as1[row_h * NH1 + h] = psh; g_ad1[row_h * NH1 + h] = pdh; }
            }
        }
    }
}

// ------------------------- CSR build
__global__ void k_zero() {
    int i = blockIdx.x * blockDim.x + threadIdx.x;
    if (i < NN) g_deg[i] = 0;
}
__global__ void k_hist(const int* __restrict__ dst) {
    int e4 = blockIdx.x * blockDim.x + threadIdx.x;
    if (e4 < EE / 4) {
        int4 d = ((const int4*)dst)[e4];
        atomicAdd(&g_deg[d.x], 1);
        atomicAdd(&g_deg[d.y], 1);
        atomicAdd(&g_deg[d.z], 1);
        atomicAdd(&g_deg[d.w], 1);
    }
}
__global__ __launch_bounds__(256) void k_part() {
    __shared__ int sm[256];
    int t = threadIdx.x, i = blockIdx.x * 256 + t;
    int d = (i < NN) ? g_deg[i] : 0;
    sm[t] = d;
    __syncthreads();
#pragma unroll
    for (int off = 1; off < 256; off <<= 1) {
        int v = (t >= off) ? sm[t - off] : 0;
        __syncthreads();
        sm[t] += v;
        __syncthreads();
    }
    if (i < NN) g_rowloc[i] = sm[t] - d;
    if (t == 255) g_bsum[blockIdx.x] = sm[255];
}
__global__ __launch_bounds__(256) void k_bscan() {
    __shared__ int sm[256];
    int t = threadIdx.x;
    int d = (t < NBLK) ? g_bsum[t] : 0;
    sm[t] = d;
    __syncthreads();
#pragma unroll
    for (int off = 1; off < 256; off <<= 1) {
        int v = (t >= off) ? sm[t - off] : 0;
        __syncthreads();
        sm[t] += v;
        __syncthreads();
    }
    if (t < NBLK) g_boff[t] = sm[t] - d;
    if (t == NBLK - 1) g_rowptr[NN] = sm[t];
}
__global__ void k_fix() {
    int i = blockIdx.x * blockDim.x + threadIdx.x;
    if (i < NN) {
        int rp = g_rowloc[i] + g_boff[blockIdx.x];
        g_rowptr[i] = rp;
        g_cursor[i] = rp;
    }
}
__global__ void k_scatter(const int* __restrict__ src, const int* __restrict__ dst) {
    int e4 = blockIdx.x * blockDim.x + threadIdx.x;
    if (e4 < EE / 4) {
        int4 s = ((const int4*)src)[e4];
        int4 d = ((const int4*)dst)[e4];
        g_col[atomicAdd(&g_cursor[d.x], 1)] = s.x;
        g_col[atomicAdd(&g_cursor[d.y], 1)] = s.y;
        g_col[atomicAdd(&g_cursor[d.z], 1)] = s.z;
        g_col[atomicAdd(&g_cursor[d.w], 1)] = s.w;
    }
}

// ------------------------- layer-1 aggregation + fused layer-2 linear/att
// one warp per dst node; half-warp per edge, float4 channels per lane
__global__ __launch_bounds__(256) void k_agg1(const float* __restrict__ b1,
                                              const float* __restrict__ W2,
                                              const float* __restrict__ att_s,
                                              const float* __restrict__ att_d) {
    __shared__ float swt[8][8][36];   // [warp][head][edge slot]
    __shared__ int   ssrc[8][32];
    __shared__ float sW2[F1 * C2];
    __shared__ float sAs2[C2], sAd2[C2];

    for (int idx = threadIdx.x; idx < F1 * C2; idx += 256) sW2[idx] = W2[idx];
    if (threadIdx.x < C2) {
        sAs2[threadIdx.x] = att_s[threadIdx.x];
        sAd2[threadIdx.x] = att_d[threadIdx.x];
    }
    __syncthreads();

    const int w    = threadIdx.x >> 5;
    const int lane = threadIdx.x & 31;
    const int node = blockIdx.x * 8 + w;
    if (node >= NN) return;
    const int beg   = g_rowptr[node];
    const int deg   = g_rowptr[node + 1] - beg;
    const int total = deg + 1;

    float4 ad0 = *(const float4*)&g_ad1[node * 8];
    float4 ad1 = *(const float4*)&g_ad1[node * 8 + 4];
    float adr[8] = { ad0.x, ad0.y, ad0.z, ad0.w, ad1.x, ad1.y, ad1.z, ad1.w };

    const int half = lane >> 4;     // which edge of the pair
    const int qc   = lane & 15;     // channel quad: channels qc*4..qc*4+3
    const int hl2  = qc >> 1;       // head of my channels

    float4 acc = make_float4(0.f, 0.f, 0.f, 0.f);
    float ssum[8];
#pragma unroll
    for (int h = 0; h < 8; h++) ssum[h] = 0.f;

    for (int k0 = 0; k0 < total; k0 += 32) {
        int kk = k0 + lane;
        __syncwarp();
        if (kk < total) {
            int srcn = (kk < deg) ? g_col[beg + kk] : node;
            float4 s0 = *(const float4*)&g_as1[srcn * 8];
            float4 s1 = *(const float4*)&g_as1[srcn * 8 + 4];
            float lg[8] = { s0.x + adr[0], s0.y + adr[1], s0.z + adr[2], s0.w + adr[3],
                            s1.x + adr[4], s1.y + adr[5], s1.z + adr[6], s1.w + adr[7] };
#pragma unroll
            for (int h = 0; h < 8; h++) {
                float wt = __expf(leaky(lg[h]));
                ssum[h] += wt;
                swt[w][h][lane] = wt;
            }
            ssrc[w][lane] = srcn;
        } else {
#pragma unroll
            for (int h = 0; h < 8; h++) swt[w][h][lane] = 0.f;
            ssrc[w][lane] = node;
        }
        __syncwarp();
        int lim   = min(32, total - k0);
        int pairs = (lim + 1) >> 1;
#pragma unroll 4
        for (int j = 0; j < pairs; j++) {
            int e    = 2 * j + half;
            int srcn = ssrc[w][e];
            float wt = swt[w][hl2][e];
            float4 hv = *(const float4*)&g_h1[srcn * F1 + qc * 4];
            acc.x += wt * hv.x;
            acc.y += wt * hv.y;
            acc.z += wt * hv.z;
            acc.w += wt * hv.w;
        }
    }
    // combine the two half-warps (same channels)
    acc.x += __shfl_xor_sync(FULLM, acc.x, 16);
    acc.y += __shfl_xor_sync(FULLM, acc.y, 16);
    acc.z += __shfl_xor_sync(FULLM, acc.z, 16);
    acc.w += __shfl_xor_sync(FULLM, acc.w, 16);

#pragma unroll
    for (int h = 0; h < 8; h++) {
#pragma unroll
        for (int off = 16; off > 0; off >>= 1)
            ssum[h] += __shfl_xor_sync(FULLM, ssum[h], off);
    }
    float myS = 0.f;
#pragma unroll
    for (int h = 0; h < 8; h++)
        if (hl2 == h) myS = ssum[h];
    float inv = __fdividef(1.0f, myS);

    // x2 quad in registers (softmax-normalize + bias + relu)
    const int cb = qc * 4;
    float v0 = fmaxf(acc.x * inv + b1[cb],     0.f);
    float v1 = fmaxf(acc.y * inv + b1[cb + 1], 0.f);
    float v2 = fmaxf(acc.z * inv + b1[cb + 2], 0.f);
    float v3 = fmaxf(acc.w * inv + b1[cb + 3], 0.f);

    // fused layer-2 linear: h2 = x2 @ W2  (+ attention coefficients)
    const int cA = lane;
    const int cB = lane + 32;
    const bool has1 = (lane < 8);
    float a0 = 0.f, a1 = 0.f;
#pragma unroll
    for (int kk = 0; kk < 16; kk++) {
        float x0 = __shfl_sync(FULLM, v0, kk);
        float x1 = __shfl_sync(FULLM, v1, kk);
        float x2 = __shfl_sync(FULLM, v2, kk);
        float x3 = __shfl_sync(FULLM, v3, kk);
        a0 += x0 * sW2[(4 * kk) * C2 + cA] + x1 * sW2[(4 * kk + 1) * C2 + cA]
            + x2 * sW2[(4 * kk + 2) * C2 + cA] + x3 * sW2[(4 * kk + 3) * C2 + cA];
        if (has1)
            a1 += x0 * sW2[(4 * kk) * C2 + cB] + x1 * sW2[(4 * kk + 1) * C2 + cB]
                + x2 * sW2[(4 * kk + 2) * C2 + cB] + x3 * sW2[(4 * kk + 3) * C2 + cB];
    }
    g_h2[node * C2 + cA] = a0;
    if (has1) g_h2[node * C2 + cB] = a1;

    float ps = a0 * sAs2[cA] + (has1 ? a1 * sAs2[cB] : 0.f);
    float pd = a0 * sAd2[cA] + (has1 ? a1 * sAd2[cB] : 0.f);
#pragma unroll
    for (int off = 16; off > 0; off >>= 1) {
        ps += __shfl_xor_sync(FULLM, ps, off);
        pd += __shfl_xor_sync(FULLM, pd, off);
    }
    if (lane == 0) { g_as2[node] = ps; g_ad2[node] = pd; }
}

// ------------------------- layer-2 aggregation + bias + log_softmax (warp/node)
__global__ __launch_bounds__(256) void k_agg2(const float* __restrict__ b2,
                                              float* __restrict__ out) {
    __shared__ float swt[8][32];
    __shared__ int   ssrc[8][32];
    const int w    = threadIdx.x >> 5;
    const int lane = threadIdx.x & 31;
    const int node = blockIdx.x * 8 + w;
    if (node >= NN) return;
    const int beg   = g_rowptr[node];
    const int deg   = g_rowptr[node + 1] - beg;
    const int total = deg + 1;
    const float adn = g_ad2[node];

    const int c0 = lane;
    const int c1 = lane + 32;
    const bool has1 = (c1 < C2);
    float acc0 = 0.f, acc1 = 0.f, ssum = 0.f;
    for (int k0 = 0; k0 < total; k0 += 32) {
        int kk = k0 + lane;
        __syncwarp();
        if (kk < total) {
            int srcn = (kk < deg) ? g_col[beg + kk] : node;
            float wt = __expf(leaky(g_as2[srcn] + adn));
            ssum += wt;
            swt[w][lane]  = wt;
            ssrc[w][lane] = srcn;
        } else {
            swt[w][lane]  = 0.f;
            ssrc[w][lane] = node;
        }
        __syncwarp();
        int lim = min(32, total - k0);
#pragma unroll 4
        for (int j = 0; j < lim; j++) {
            int srcn = ssrc[w][j];
            float wt = swt[w][j];
            acc0 += wt * g_h2[srcn * C2 + c0];
            if (has1) acc1 += wt * g_h2[srcn * C2 + c1];
        }
    }
#pragma unroll
    for (int off = 16; off > 0; off >>= 1)
        ssum += __shfl_xor_sync(FULLM, ssum, off);
    float inv = __fdividef(1.0f, ssum);

    float o0 = acc0 * inv + b2[c0];
    float o1 = has1 ? (acc1 * inv + b2[c1]) : -1e30f;

    float mx = fmaxf(o0, o1);
#pragma unroll
    for (int off = 16; off > 0; off >>= 1)
        mx = fmaxf(mx, __shfl_xor_sync(FULLM, mx, off));
    float se = __expf(o0 - mx) + (has1 ? __expf(o1 - mx) : 0.f);
#pragma unroll
    for (int off = 16; off > 0; off >>= 1)
        se += __shfl_xor_sync(FULLM, se, off);
    float lse = mx + __logf(se);

    out[node * C2 + c0] = o0 - lse;
    if (has1) out[node * C2 + c1] = o1 - lse;
}

// ------------------------- launch
extern "C" void kernel_launch(void* const* d_in, const int* in_sizes, int n_in,
                              void* d_out, int out_size) {
    const float* x        = (const float*)d_in[0];
    const int*   ei       = (const int*)d_in[1];
    const float* W1       = (const float*)d_in[2];
    const float* att_src1 = (const float*)d_in[3];
    const float* att_dst1 = (const float*)d_in[4];
    const float* b1       = (const float*)d_in[5];
    const float* W2       = (const float*)d_in[6];
    const float* att_src2 = (const float*)d_in[7];
    const float* att_dst2 = (const float*)d_in[8];
    const float* b2       = (const float*)d_in[9];
    float* out = (float*)d_out;

    const int* src = ei;
    const int* dst = ei + EE;

    // CSR build
    k_zero<<<(NN + 255) / 256, 256>>>();
    k_hist<<<(EE / 4 + 255) / 256, 256>>>(dst);
    k_part<<<NBLK, 256>>>();
    k_bscan<<<1, 256>>>();
    k_fix<<<NBLK, 256>>>();
    k_scatter<<<(EE / 4 + 255) / 256, 256>>>(src, dst);

    // layer 1 (tf32 tensor-core GEMM + fused att coeffs)
    k_gemm1<<<(NN + 127) / 128, 256>>>(x, W1, att_src1, att_dst1);

    // layer-1 aggregation fused with layer-2 linear + att coeffs
    k_agg1<<<(NN + 7) / 8, 256>>>(b1, W2, att_src2, att_dst2);

    // layer-2 aggregation + log_softmax
    k_agg2<<<(NN + 7) / 8, 256>>>(b2, out);
}